// round 5
// baseline (speedup 1.0000x reference)
#include <cuda_runtime.h>
#include <cuda_fp16.h>

#define NN 100000
#define NB 32      // n (bases)
#define MM 16      // m (clusters)
#define KK 32      // k (neighbours)

typedef unsigned long long u64;

// ---- packed f32x2 helpers (Blackwell; ptxas won't auto-fuse these) ----
__device__ __forceinline__ u64 pk2(float lo, float hi) {
    u64 r; asm("mov.b64 %0,{%1,%2};" : "=l"(r) : "f"(lo), "f"(hi)); return r;
}
__device__ __forceinline__ void upk2(u64 v, float& lo, float& hi) {
    asm("mov.b64 {%0,%1},%2;" : "=f"(lo), "=f"(hi) : "l"(v));
}
__device__ __forceinline__ u64 fma2(u64 a, u64 b, u64 c) {
    u64 d; asm("fma.rn.f32x2 %0,%1,%2,%3;" : "=l"(d) : "l"(a), "l"(b), "l"(c)); return d;
}
__device__ __forceinline__ u64 mul2(u64 a, u64 b) {
    u64 d; asm("mul.rn.f32x2 %0,%1,%2;" : "=l"(d) : "l"(a), "l"(b)); return d;
}
__device__ __forceinline__ u64 add2(u64 a, u64 b) {
    u64 d; asm("add.rn.f32x2 %0,%1,%2;" : "=l"(d) : "l"(a), "l"(b)); return d;
}
#define ONE2 0x3F8000003F800000ULL
// 2*relu(x) = x + |x| (exact)
__device__ __forceinline__ u64 relu2x(u64 t) {
    return add2(t, t & 0x7FFFFFFF7FFFFFFFULL);
}

// ---- device scratch (no allocations allowed) ----
__device__ float g_encPart[4 * NB];
__device__ float g_encoded[NB];
__device__ float g_S[NB * KK];          // stores 2*S (cancels k_out's doubled relu)
__device__ __align__(16) float g_a[MM * NB];
__device__ __align__(128) __half g_decTh[(size_t)NN * NB];  // decoder^T fp16 [N][32]

// ---- k1: fused transpose (blocks 0..3124) + encode partials ----
__global__ void k_prep(const float* __restrict__ dec, const float* __restrict__ x,
                       const float* __restrict__ W) {
    if (blockIdx.x < NN / 32) {
        __shared__ float tile[32][33];
        int p0 = blockIdx.x * 32;
        int tx = threadIdx.x & 31, ty = threadIdx.x >> 5;
        #pragma unroll
        for (int r = 0; r < 4; r++) {
            int i = ty + 8 * r;
            tile[i][tx] = dec[(size_t)i * NN + p0 + tx];
        }
        __syncthreads();
        #pragma unroll
        for (int r = 0; r < 4; r++) {
            int row = ty + 8 * r;
            g_decTh[(size_t)(p0 + row) * NB + tx] = __float2half(tile[tx][row]);
        }
    } else {
        int e = blockIdx.x - NN / 32;
        int ck = e >> 5, i = e & 31;
        const float* Wr = W + (size_t)i * NN;
        int p0 = ck * (NN / 4);
        float acc = 0.f;
        for (int p = p0 + threadIdx.x; p < p0 + NN / 4; p += 256)
            acc = fmaf(x[p], Wr[p], acc);
        #pragma unroll
        for (int o = 16; o; o >>= 1) acc += __shfl_xor_sync(0xffffffffu, acc, o);
        __shared__ float s[8];
        if ((threadIdx.x & 31) == 0) s[threadIdx.x >> 5] = acc;
        __syncthreads();
        if (threadIdx.x == 0) {
            float t = 0.f;
            #pragma unroll
            for (int j = 0; j < 8; j++) t += s[j];
            g_encPart[ck * NB + i] = t;
        }
    }
}

// ---- k2: finalize encoded, zero S, warp-per-j bw linear -> g_a ----
__global__ void k_bw(const float* __restrict__ bwW, const float* __restrict__ bwB,
                     const float* __restrict__ encB) {
    __shared__ float enc[NB];
    int tid = threadIdx.x;
    if (tid < NB) {
        float e = encB[tid];
        #pragma unroll
        for (int c2 = 0; c2 < 4; c2++) e += g_encPart[c2 * NB + tid];
        enc[tid] = e;
        if (blockIdx.x == 0) g_encoded[tid] = e;
    }
    if (blockIdx.x == 0 && tid < NB * KK) g_S[tid] = 0.f;
    __syncthreads();
    int w = tid >> 5, lane = tid & 31;
    int j = blockIdx.x * 32 + w;
    float z = bwW[j * NB + lane] * enc[lane];
    #pragma unroll
    for (int o = 16; o; o >>= 1) z += __shfl_xor_sync(0xffffffffu, z, o);
    if (lane == 0) {
        z += bwB[j];
        float s = 1.f / (1.f + expf(-z));
        float t = s * (100.0f / 60.0f);
        int i = j >> 4, c = j & 15;
        g_a[c * NB + i] = 1.f / (t * t);
    }
}

// ---- k3: g_S[i][kk] = 2 * sum_p relu(1 - d^2 * a[i, label[p]]) ----
__global__ void __launch_bounds__(256, 6)
k_sumS(const float* __restrict__ nd, const int* __restrict__ lab) {
    __shared__ __align__(16) float sa[MM * NB];
    __shared__ float bS[NB * KK];
    for (int t = threadIdx.x; t < MM * NB; t += 256) sa[t] = g_a[t];
    for (int t = threadIdx.x; t < NB * KK; t += 256) bS[t] = 0.f;
    __syncthreads();

    int lane = threadIdx.x & 31;                    // lane == kk
    int gw = (blockIdx.x * 256 + threadIdx.x) >> 5;
    int h = gw & 1;                                 // which i-half
    int stream = gw >> 1;
    const int nstream = (gridDim.x * 8) >> 1;

    u64 acc2[8];
    #pragma unroll
    for (int j = 0; j < 8; j++) acc2[j] = 0ULL;

    int p = stream;
    if (p < NN) {
        float d = nd[p * KK + lane];
        int c = lab[p];
        while (true) {
            int pn = p + nstream;
            float dn = 0.f; int cn = 0;
            if (pn < NN) { dn = nd[pn * KK + lane]; cn = lab[pn]; }
            float md2 = -d * d;
            u64 m2 = pk2(md2, md2);
            const float4* a4 = (const float4*)&sa[c * NB + h * 16];
            #pragma unroll
            for (int q = 0; q < 4; q++) {
                float4 av = a4[q];
                u64 A0 = pk2(av.x, av.y), A1 = pk2(av.z, av.w);
                acc2[q * 2 + 0] = add2(acc2[q * 2 + 0], relu2x(fma2(m2, A0, ONE2)));
                acc2[q * 2 + 1] = add2(acc2[q * 2 + 1], relu2x(fma2(m2, A1, ONE2)));
            }
            if (pn >= NN) break;
            p = pn; d = dn; c = cn;
        }
    }
    #pragma unroll
    for (int j = 0; j < 8; j++) {
        float lo, hi; upk2(acc2[j], lo, hi);
        atomicAdd(&bS[(h * 16 + j * 2 + 0) * KK + lane], lo);
        atomicAdd(&bS[(h * 16 + j * 2 + 1) * KK + lane], hi);
    }
    __syncthreads();
    for (int t = threadIdx.x; t < NB * KK; t += 256)
        atomicAdd(&g_S[t], bS[t]);
}

// ---- k4: out[p] = sum_kk sum_i E*relu(1-d^2 a)*decTh[nid] ----
// E_stored = enc/(2S) so the doubled relu cancels exactly.
__global__ void __launch_bounds__(256, 4)
k_out(const float* __restrict__ nd, const int* __restrict__ nid,
      const int* __restrict__ lab, float* __restrict__ out) {
    __shared__ __align__(16) float sa[MM * NB];
    __shared__ __align__(16) float sE[KK * NB];     // E/2 [kk][i]
    for (int t = threadIdx.x; t < MM * NB; t += blockDim.x) sa[t] = g_a[t];
    for (int t = threadIdx.x; t < KK * NB; t += blockDim.x) {
        int i = t & 31, kk = t >> 5;
        sE[t] = g_encoded[i] / g_S[i * KK + kk];    // g_S = 2S -> E/2
    }
    __syncthreads();

    int lane = threadIdx.x & 31;
    int warp = (blockIdx.x * blockDim.x + threadIdx.x) >> 5;
    int nwarp = (gridDim.x * blockDim.x) >> 5;
    int r = lane & 3;        // i-chunk (8 halves = 16B of the 64B row)
    int g = lane >> 2;       // kk subgroup (8 per round)
    const float4* sa4 = (const float4*)sa;
    const float4* sE4 = (const float4*)sE;

    // hoist E/2 into registers as packed f32x2: 16 pairs
    u64 Ep[16];
    #pragma unroll
    for (int t = 0; t < 4; t++) {
        int kk = t * 8 + g;
        float4 e0 = sE4[kk * 8 + r * 2];
        float4 e1 = sE4[kk * 8 + r * 2 + 1];
        Ep[t * 4 + 0] = pk2(e0.x, e0.y);
        Ep[t * 4 + 1] = pk2(e0.z, e0.w);
        Ep[t * 4 + 2] = pk2(e1.x, e1.y);
        Ep[t * 4 + 3] = pk2(e1.z, e1.w);
    }

    int p = warp;
    if (p >= NN) return;
    float d_r = nd[p * KK + lane];
    int   q_r = nid[p * KK + lane];
    int   c   = lab[p];

    while (true) {
        int pn = p + nwarp;
        float dn = 0.f; int qn = 0, cn = 0;
        if (pn < NN) {
            dn = nd[pn * KK + lane];
            qn = nid[pn * KK + lane];
            cn = lab[pn];
        }

        float4 a0 = sa4[c * 8 + r * 2];
        float4 a1 = sa4[c * 8 + r * 2 + 1];
        u64 A[4];
        A[0] = pk2(a0.x, a0.y); A[1] = pk2(a0.z, a0.w);
        A[2] = pk2(a1.x, a1.y); A[3] = pk2(a1.z, a1.w);
        u64 acc0 = 0ULL, acc1 = 0ULL;

        // 2-stage gather pipeline over 4 rounds
        float d0 = __shfl_sync(0xffffffffu, d_r, g);
        int   q0 = __shfl_sync(0xffffffffu, q_r, g);
        uint4 hv = *(const uint4*)&g_decTh[(size_t)q0 * NB + r * 8];
        float dcur = d0;
        #pragma unroll
        for (int t = 0; t < 4; t++) {
            uint4 hvn; float dnx = 0.f;
            if (t < 3) {
                int kk = (t + 1) * 8 + g;
                dnx = __shfl_sync(0xffffffffu, d_r, kk);
                int q = __shfl_sync(0xffffffffu, q_r, kk);
                hvn = *(const uint4*)&g_decTh[(size_t)q * NB + r * 8];
            }
            float md2 = -dcur * dcur;
            u64 m2 = pk2(md2, md2);
            u64 W0 = relu2x(fma2(m2, A[0], ONE2));
            u64 W1 = relu2x(fma2(m2, A[1], ONE2));
            u64 W2 = relu2x(fma2(m2, A[2], ONE2));
            u64 W3 = relu2x(fma2(m2, A[3], ONE2));
            float2 f0 = __half22float2(*(__half2*)&hv.x);
            float2 f1 = __half22float2(*(__half2*)&hv.y);
            float2 f2 = __half22float2(*(__half2*)&hv.z);
            float2 f3 = __half22float2(*(__half2*)&hv.w);
            acc0 = fma2(mul2(W0, pk2(f0.x, f0.y)), Ep[t * 4 + 0], acc0);
            acc1 = fma2(mul2(W1, pk2(f1.x, f1.y)), Ep[t * 4 + 1], acc1);
            acc0 = fma2(mul2(W2, pk2(f2.x, f2.y)), Ep[t * 4 + 2], acc0);
            acc1 = fma2(mul2(W3, pk2(f3.x, f3.y)), Ep[t * 4 + 3], acc1);
            hv = hvn; dcur = dnx;
        }
        u64 at = add2(acc0, acc1);
        float lo, hi; upk2(at, lo, hi);
        float acc = lo + hi;
        #pragma unroll
        for (int o = 16; o; o >>= 1) acc += __shfl_xor_sync(0xffffffffu, acc, o);
        if (lane == 0) out[p] = acc;

        if (pn >= NN) break;
        p = pn; d_r = dn; q_r = qn; c = cn;
    }
}

extern "C" void kernel_launch(void* const* d_in, const int* in_sizes, int n_in,
                              void* d_out, int out_size) {
    const float* x    = (const float*)d_in[0];
    const float* encW = (const float*)d_in[1];
    const float* encB = (const float*)d_in[2];
    const float* dec  = (const float*)d_in[3];
    const float* bwW  = (const float*)d_in[4];
    const float* bwB  = (const float*)d_in[5];
    const float* nd   = (const float*)d_in[6];
    const int*   nidp = (const int*)d_in[7];
    const int*   lab  = (const int*)d_in[8];
    float* out = (float*)d_out;

    k_prep<<<NN / 32 + 128, 256>>>(dec, x, encW);
    k_bw<<<16, 1024>>>(bwW, bwB, encB);
    k_sumS<<<888, 256>>>(nd, lab);
    k_out<<<592, 256>>>(nd, nidp, lab, out);
}

// round 6
// speedup vs baseline: 1.0008x; 1.0008x over previous
#include <cuda_runtime.h>
#include <cuda_fp16.h>

#define NN 100000
#define NB 32      // n (bases)
#define MM 16      // m (clusters)
#define KK 32      // k (neighbours)

// ---- device scratch (no allocations allowed) ----
__device__ float g_encPart[4 * NB];
__device__ float g_encoded[NB];
__device__ float g_S[NB * KK];
__device__ __align__(16) float g_a[MM * NB];
__device__ __align__(128) __half g_decTh[(size_t)NN * NB];  // decoder^T fp16 [N][32]

// ---- k1: fused transpose (blocks 0..3124) + encode partials ----
__global__ void k_prep(const float* __restrict__ dec, const float* __restrict__ x,
                       const float* __restrict__ W) {
    if (blockIdx.x < NN / 32) {
        __shared__ float tile[32][33];
        int p0 = blockIdx.x * 32;
        int tx = threadIdx.x & 31, ty = threadIdx.x >> 5;
        #pragma unroll
        for (int r = 0; r < 4; r++) {
            int i = ty + 8 * r;
            tile[i][tx] = dec[(size_t)i * NN + p0 + tx];
        }
        __syncthreads();
        #pragma unroll
        for (int r = 0; r < 4; r++) {
            int row = ty + 8 * r;
            g_decTh[(size_t)(p0 + row) * NB + tx] = __float2half(tile[tx][row]);
        }
    } else {
        int e = blockIdx.x - NN / 32;
        int ck = e >> 5, i = e & 31;
        const float* Wr = W + (size_t)i * NN;
        int p0 = ck * (NN / 4);
        float acc = 0.f;
        for (int p = p0 + threadIdx.x; p < p0 + NN / 4; p += 256)
            acc = fmaf(x[p], Wr[p], acc);
        #pragma unroll
        for (int o = 16; o; o >>= 1) acc += __shfl_xor_sync(0xffffffffu, acc, o);
        __shared__ float s[8];
        if ((threadIdx.x & 31) == 0) s[threadIdx.x >> 5] = acc;
        __syncthreads();
        if (threadIdx.x == 0) {
            float t = 0.f;
            #pragma unroll
            for (int j = 0; j < 8; j++) t += s[j];
            g_encPart[ck * NB + i] = t;
        }
    }
}

// ---- k2: finalize encoded, zero S, warp-per-j bw linear -> g_a ----
__global__ void k_bw(const float* __restrict__ bwW, const float* __restrict__ bwB,
                     const float* __restrict__ encB) {
    __shared__ float enc[NB];
    int tid = threadIdx.x;
    if (tid < NB) {
        float e = encB[tid];
        #pragma unroll
        for (int c2 = 0; c2 < 4; c2++) e += g_encPart[c2 * NB + tid];
        enc[tid] = e;
        if (blockIdx.x == 0) g_encoded[tid] = e;
    }
    if (blockIdx.x == 0 && tid < NB * KK) g_S[tid] = 0.f;
    __syncthreads();
    int w = tid >> 5, lane = tid & 31;
    int j = blockIdx.x * 32 + w;
    float z = bwW[j * NB + lane] * enc[lane];
    #pragma unroll
    for (int o = 16; o; o >>= 1) z += __shfl_xor_sync(0xffffffffu, z, o);
    if (lane == 0) {
        z += bwB[j];
        float s = 1.f / (1.f + expf(-z));
        float t = s * (100.0f / 60.0f);
        int i = j >> 4, c = j & 15;
        g_a[c * NB + i] = 1.f / (t * t);
    }
}

// ---- k3: S[i][kk] = sum_p relu(1 - d^2 * a[i, label[p]])  (R4 scalar form) ----
__global__ void __launch_bounds__(256, 6)
k_sumS(const float* __restrict__ nd, const int* __restrict__ lab) {
    __shared__ __align__(16) float sa[MM * NB];
    __shared__ float bS[NB * KK];
    for (int t = threadIdx.x; t < MM * NB; t += 256) sa[t] = g_a[t];
    for (int t = threadIdx.x; t < NB * KK; t += 256) bS[t] = 0.f;
    __syncthreads();

    int lane = threadIdx.x & 31;                    // lane == kk
    int gw = (blockIdx.x * 256 + threadIdx.x) >> 5;
    int h = gw & 1;                                 // which i-half
    int stream = gw >> 1;
    const int nstream = (gridDim.x * 8) >> 1;

    float acc[16];
    #pragma unroll
    for (int ii = 0; ii < 16; ii++) acc[ii] = 0.f;

    int p = stream;
    if (p < NN) {
        float d = nd[p * KK + lane];
        int c = lab[p];
        while (true) {
            int pn = p + nstream;
            float dn = 0.f; int cn = 0;
            if (pn < NN) { dn = nd[pn * KK + lane]; cn = lab[pn]; }
            float md2 = -d * d;
            const float4* a4 = (const float4*)&sa[c * NB + h * 16];
            #pragma unroll
            for (int q = 0; q < 4; q++) {
                float4 av = a4[q];
                acc[q * 4 + 0] += fmaxf(fmaf(md2, av.x, 1.f), 0.f);
                acc[q * 4 + 1] += fmaxf(fmaf(md2, av.y, 1.f), 0.f);
                acc[q * 4 + 2] += fmaxf(fmaf(md2, av.z, 1.f), 0.f);
                acc[q * 4 + 3] += fmaxf(fmaf(md2, av.w, 1.f), 0.f);
            }
            if (pn >= NN) break;
            p = pn; d = dn; c = cn;
        }
    }
    #pragma unroll
    for (int ii = 0; ii < 16; ii++)
        atomicAdd(&bS[(h * 16 + ii) * KK + lane], acc[ii]);
    __syncthreads();
    for (int t = threadIdx.x; t < NB * KK; t += 256)
        atomicAdd(&g_S[t], bS[t]);
}

// ---- k4: out[p] = sum_kk sum_i E[i,kk]*relu(1-d^2*a[i,c])*decTh[nid][i] ----
// E hoisted to registers as half2 scaled by 2^10 (halves reg cost of hoist);
// 5 blocks/SM for 62% occupancy. Scale removed exactly at the end.
__global__ void __launch_bounds__(256, 5)
k_out(const float* __restrict__ nd, const int* __restrict__ nid,
      const int* __restrict__ lab, float* __restrict__ out) {
    __shared__ __align__(16) float sa[MM * NB];
    __shared__ __align__(16) float sE[KK * NB];     // 1024*E [kk][i]
    for (int t = threadIdx.x; t < MM * NB; t += blockDim.x) sa[t] = g_a[t];
    for (int t = threadIdx.x; t < KK * NB; t += blockDim.x) {
        int i = t & 31, kk = t >> 5;
        sE[t] = 1024.0f * g_encoded[i] / g_S[i * KK + kk];
    }
    __syncthreads();

    int lane = threadIdx.x & 31;
    int warp = (blockIdx.x * blockDim.x + threadIdx.x) >> 5;
    int nwarp = (gridDim.x * blockDim.x) >> 5;
    int r = lane & 3;        // i-chunk (8 halves = 16B of the 64B row)
    int g = lane >> 2;       // kk subgroup (8 per round)
    const float4* sa4 = (const float4*)sa;
    const float4* sE4 = (const float4*)sE;

    // hoist scaled E into 16 half2 registers
    __half2 Eh[16];
    #pragma unroll
    for (int t = 0; t < 4; t++) {
        int kk = t * 8 + g;
        float4 e0 = sE4[kk * 8 + r * 2];
        float4 e1 = sE4[kk * 8 + r * 2 + 1];
        Eh[t * 4 + 0] = __floats2half2_rn(e0.x, e0.y);
        Eh[t * 4 + 1] = __floats2half2_rn(e0.z, e0.w);
        Eh[t * 4 + 2] = __floats2half2_rn(e1.x, e1.y);
        Eh[t * 4 + 3] = __floats2half2_rn(e1.z, e1.w);
    }

    int p = warp;
    if (p >= NN) return;
    float d_r = nd[p * KK + lane];
    int   q_r = nid[p * KK + lane];
    int   c   = lab[p];

    while (true) {
        // prefetch next point's row data
        int pn = p + nwarp;
        float dn = 0.f; int qn = 0, cn = 0;
        if (pn < NN) {
            dn = nd[pn * KK + lane];
            qn = nid[pn * KK + lane];
            cn = lab[pn];
        }

        float4 a0 = sa4[c * 8 + r * 2];
        float4 a1 = sa4[c * 8 + r * 2 + 1];
        float acc = 0.f;

        // 2-stage gather pipeline over the 4 rounds
        float d0 = __shfl_sync(0xffffffffu, d_r, g);
        int   q0 = __shfl_sync(0xffffffffu, q_r, g);
        uint4 hv = *(const uint4*)&g_decTh[(size_t)q0 * NB + r * 8];
        float dcur = d0;
        #pragma unroll
        for (int t = 0; t < 4; t++) {
            uint4 hvn; float dnx = 0.f;
            if (t < 3) {
                int kk = (t + 1) * 8 + g;
                dnx = __shfl_sync(0xffffffffu, d_r, kk);
                int q = __shfl_sync(0xffffffffu, q_r, kk);
                hvn = *(const uint4*)&g_decTh[(size_t)q * NB + r * 8];
            }
            float md2 = -dcur * dcur;
            float2 f0 = __half22float2(*(__half2*)&hv.x);
            float2 f1 = __half22float2(*(__half2*)&hv.y);
            float2 f2 = __half22float2(*(__half2*)&hv.z);
            float2 f3 = __half22float2(*(__half2*)&hv.w);
            float2 E0 = __half22float2(Eh[t * 4 + 0]);
            float2 E1 = __half22float2(Eh[t * 4 + 1]);
            float2 E2 = __half22float2(Eh[t * 4 + 2]);
            float2 E3 = __half22float2(Eh[t * 4 + 3]);
            float w0 = fmaxf(fmaf(md2, a0.x, 1.f), 0.f);
            float w1 = fmaxf(fmaf(md2, a0.y, 1.f), 0.f);
            float w2 = fmaxf(fmaf(md2, a0.z, 1.f), 0.f);
            float w3 = fmaxf(fmaf(md2, a0.w, 1.f), 0.f);
            float w4 = fmaxf(fmaf(md2, a1.x, 1.f), 0.f);
            float w5 = fmaxf(fmaf(md2, a1.y, 1.f), 0.f);
            float w6 = fmaxf(fmaf(md2, a1.z, 1.f), 0.f);
            float w7 = fmaxf(fmaf(md2, a1.w, 1.f), 0.f);
            acc = fmaf(w0 * E0.x, f0.x, acc);
            acc = fmaf(w1 * E0.y, f0.y, acc);
            acc = fmaf(w2 * E1.x, f1.x, acc);
            acc = fmaf(w3 * E1.y, f1.y, acc);
            acc = fmaf(w4 * E2.x, f2.x, acc);
            acc = fmaf(w5 * E2.y, f2.y, acc);
            acc = fmaf(w6 * E3.x, f3.x, acc);
            acc = fmaf(w7 * E3.y, f3.y, acc);
            hv = hvn; dcur = dnx;
        }
        #pragma unroll
        for (int o = 16; o; o >>= 1) acc += __shfl_xor_sync(0xffffffffu, acc, o);
        if (lane == 0) out[p] = acc * (1.0f / 1024.0f);

        if (pn >= NN) break;
        p = pn; d_r = dn; q_r = qn; c = cn;
    }
}

extern "C" void kernel_launch(void* const* d_in, const int* in_sizes, int n_in,
                              void* d_out, int out_size) {
    const float* x    = (const float*)d_in[0];
    const float* encW = (const float*)d_in[1];
    const float* encB = (const float*)d_in[2];
    const float* dec  = (const float*)d_in[3];
    const float* bwW  = (const float*)d_in[4];
    const float* bwB  = (const float*)d_in[5];
    const float* nd   = (const float*)d_in[6];
    const int*   nidp = (const int*)d_in[7];
    const int*   lab  = (const int*)d_in[8];
    float* out = (float*)d_out;

    k_prep<<<NN / 32 + 128, 256>>>(dec, x, encW);
    k_bw<<<16, 1024>>>(bwW, bwB, encB);
    k_sumS<<<888, 256>>>(nd, lab);
    k_out<<<740, 256>>>(nd, nidp, lab, out);
}

// round 7
// speedup vs baseline: 1.0225x; 1.0217x over previous
#include <cuda_runtime.h>
#include <cuda_fp16.h>

#define NN 100000
#define NB 32      // n (bases)
#define MM 16      // m (clusters)
#define KK 32      // k (neighbours)

// ---- device scratch (no allocations allowed) ----
__device__ float g_encPart[4 * NB];
__device__ float g_encoded[NB];
__device__ float g_S[NB * KK];
__device__ __align__(16) float g_a[MM * NB];
__device__ __align__(128) __half g_decTh[(size_t)NN * NB];  // decoder^T fp16 [N][32]

// ---- k1: fused transpose (blocks 0..3124) + encode partials ----
__global__ void k_prep(const float* __restrict__ dec, const float* __restrict__ x,
                       const float* __restrict__ W) {
    if (blockIdx.x < NN / 32) {
        __shared__ float tile[32][33];
        int p0 = blockIdx.x * 32;
        int tx = threadIdx.x & 31, ty = threadIdx.x >> 5;
        #pragma unroll
        for (int r = 0; r < 4; r++) {
            int i = ty + 8 * r;
            tile[i][tx] = dec[(size_t)i * NN + p0 + tx];
        }
        __syncthreads();
        #pragma unroll
        for (int r = 0; r < 4; r++) {
            int row = ty + 8 * r;
            g_decTh[(size_t)(p0 + row) * NB + tx] = __float2half(tile[tx][row]);
        }
    } else {
        int e = blockIdx.x - NN / 32;
        int ck = e >> 5, i = e & 31;
        const float* Wr = W + (size_t)i * NN;
        int p0 = ck * (NN / 4);
        float acc = 0.f;
        for (int p = p0 + threadIdx.x; p < p0 + NN / 4; p += 256)
            acc = fmaf(x[p], Wr[p], acc);
        #pragma unroll
        for (int o = 16; o; o >>= 1) acc += __shfl_xor_sync(0xffffffffu, acc, o);
        __shared__ float s[8];
        if ((threadIdx.x & 31) == 0) s[threadIdx.x >> 5] = acc;
        __syncthreads();
        if (threadIdx.x == 0) {
            float t = 0.f;
            #pragma unroll
            for (int j = 0; j < 8; j++) t += s[j];
            g_encPart[ck * NB + i] = t;
        }
    }
}

// ---- k2: finalize encoded, zero S, warp-per-j bw linear -> g_a ----
__global__ void k_bw(const float* __restrict__ bwW, const float* __restrict__ bwB,
                     const float* __restrict__ encB) {
    __shared__ float enc[NB];
    int tid = threadIdx.x;
    if (tid < NB) {
        float e = encB[tid];
        #pragma unroll
        for (int c2 = 0; c2 < 4; c2++) e += g_encPart[c2 * NB + tid];
        enc[tid] = e;
        if (blockIdx.x == 0) g_encoded[tid] = e;
    }
    if (blockIdx.x == 0 && tid < NB * KK) g_S[tid] = 0.f;
    __syncthreads();
    int w = tid >> 5, lane = tid & 31;
    int j = blockIdx.x * 32 + w;
    float z = bwW[j * NB + lane] * enc[lane];
    #pragma unroll
    for (int o = 16; o; o >>= 1) z += __shfl_xor_sync(0xffffffffu, z, o);
    if (lane == 0) {
        z += bwB[j];
        float s = 1.f / (1.f + expf(-z));
        float t = s * (100.0f / 60.0f);
        int i = j >> 4, c = j & 15;
        g_a[c * NB + i] = 1.f / (t * t);
    }
}

// ---- k3: S[i][kk] = sum_p relu(1 - d^2 * a[i, label[p]]), w math in half2 ----
__global__ void __launch_bounds__(256, 6)
k_sumS(const float* __restrict__ nd, const int* __restrict__ lab) {
    __shared__ __half2 sah[MM * 16];     // a packed (2i,2i+1) per cluster, clamped
    __shared__ float bS[NB * KK];
    for (int t = threadIdx.x; t < MM * 16; t += 256) {
        int c = t >> 4, j = t & 15;
        float a0 = fminf(g_a[c * NB + j * 2 + 0], 60000.f);
        float a1 = fminf(g_a[c * NB + j * 2 + 1], 60000.f);
        sah[t] = __floats2half2_rn(a0, a1);
    }
    for (int t = threadIdx.x; t < NB * KK; t += 256) bS[t] = 0.f;
    __syncthreads();

    int lane = threadIdx.x & 31;                    // lane == kk
    int gw = (blockIdx.x * 256 + threadIdx.x) >> 5;
    int h = gw & 1;                                 // which i-half (16 i)
    int stream = gw >> 1;
    const int nstream = (gridDim.x * 8) >> 1;
    const __half2 one2 = __float2half2_rn(1.f);
    const __half2 zero2 = __float2half2_rn(0.f);

    float accf[16];
    #pragma unroll
    for (int ii = 0; ii < 16; ii++) accf[ii] = 0.f;
    __half2 acc2[8];
    #pragma unroll
    for (int j = 0; j < 8; j++) acc2[j] = zero2;

    int p = stream, cnt = 0;
    if (p < NN) {
        float d = nd[p * KK + lane];
        int c = lab[p];
        while (true) {
            int pn = p + nstream;
            float dn = 0.f; int cn = 0;
            if (pn < NN) { dn = nd[pn * KK + lane]; cn = lab[pn]; }
            __half2 md2h = __float2half2_rn(-d * d);
            uint4 ar0 = *(const uint4*)&sah[c * 16 + h * 8];
            uint4 ar1 = *(const uint4*)&sah[c * 16 + h * 8 + 4];
            const __half2* ah0 = (const __half2*)&ar0;
            const __half2* ah1 = (const __half2*)&ar1;
            #pragma unroll
            for (int j = 0; j < 4; j++) {
                acc2[j]     = __hadd2(acc2[j],
                                __hmax2(__hfma2(md2h, ah0[j], one2), zero2));
                acc2[j + 4] = __hadd2(acc2[j + 4],
                                __hmax2(__hfma2(md2h, ah1[j], one2), zero2));
            }
            if (++cnt == 16) {                       // bound fp16 chain length
                cnt = 0;
                #pragma unroll
                for (int j = 0; j < 8; j++) {
                    float2 f = __half22float2(acc2[j]);
                    accf[j * 2] += f.x; accf[j * 2 + 1] += f.y;
                    acc2[j] = zero2;
                }
            }
            if (pn >= NN) break;
            p = pn; d = dn; c = cn;
        }
        #pragma unroll
        for (int j = 0; j < 8; j++) {                // final flush
            float2 f = __half22float2(acc2[j]);
            accf[j * 2] += f.x; accf[j * 2 + 1] += f.y;
        }
    }
    #pragma unroll
    for (int ii = 0; ii < 16; ii++)
        atomicAdd(&bS[(h * 16 + ii) * KK + lane], accf[ii]);
    __syncthreads();
    for (int t = threadIdx.x; t < NB * KK; t += 256)
        atomicAdd(&g_S[t], bS[t]);
}

// ---- k4: out[p] = sum_kk sum_i E*relu(1-d^2 a)*decTh[nid], inner math half2 ----
// E scaled by 256 (exact power of 2, removed at the end); a clamped+packed half2.
__global__ void __launch_bounds__(256, 5)
k_out(const float* __restrict__ nd, const int* __restrict__ nid,
      const int* __restrict__ lab, float* __restrict__ out) {
    __shared__ __half2 sah[MM * 16];
    __shared__ __align__(16) float sE[KK * NB];     // 256*E [kk][i] staging
    for (int t = threadIdx.x; t < MM * 16; t += blockDim.x) {
        int c = t >> 4, j = t & 15;
        float a0 = fminf(g_a[c * NB + j * 2 + 0], 60000.f);
        float a1 = fminf(g_a[c * NB + j * 2 + 1], 60000.f);
        sah[t] = __floats2half2_rn(a0, a1);
    }
    for (int t = threadIdx.x; t < KK * NB; t += blockDim.x) {
        int i = t & 31, kk = t >> 5;
        sE[t] = 256.0f * g_encoded[i] / g_S[i * KK + kk];
    }
    __syncthreads();

    int lane = threadIdx.x & 31;
    int warp = (blockIdx.x * blockDim.x + threadIdx.x) >> 5;
    int nwarp = (gridDim.x * blockDim.x) >> 5;
    int r = lane & 3;        // i-chunk (8 halves = 16B of the 64B row)
    int g = lane >> 2;       // kk subgroup (8 per round)
    const float4* sE4 = (const float4*)sE;
    const __half2 one2 = __float2half2_rn(1.f);
    const __half2 zero2 = __float2half2_rn(0.f);

    // hoist scaled E into 16 half2 registers (born packed, used packed)
    __half2 Eh[16];
    #pragma unroll
    for (int t = 0; t < 4; t++) {
        int kk = t * 8 + g;
        float4 e0 = sE4[kk * 8 + r * 2];
        float4 e1 = sE4[kk * 8 + r * 2 + 1];
        Eh[t * 4 + 0] = __floats2half2_rn(e0.x, e0.y);
        Eh[t * 4 + 1] = __floats2half2_rn(e0.z, e0.w);
        Eh[t * 4 + 2] = __floats2half2_rn(e1.x, e1.y);
        Eh[t * 4 + 3] = __floats2half2_rn(e1.z, e1.w);
    }

    int p = warp;
    if (p >= NN) return;
    float d_r = nd[p * KK + lane];
    int   q_r = nid[p * KK + lane];
    int   c   = lab[p];

    while (true) {
        int pn = p + nwarp;
        float dn = 0.f; int qn = 0, cn = 0;
        if (pn < NN) {
            dn = nd[pn * KK + lane];
            qn = nid[pn * KK + lane];
            cn = lab[pn];
        }

        // this lane's 4 half2 of a (8 i-values) for this point's cluster
        uint4 araw = *(const uint4*)&sah[c * 16 + r * 4];
        const __half2* ah = (const __half2*)&araw;
        float acc = 0.f;

        // 2-stage gather pipeline over the 4 rounds
        float d0 = __shfl_sync(0xffffffffu, d_r, g);
        int   q0 = __shfl_sync(0xffffffffu, q_r, g);
        uint4 hv = *(const uint4*)&g_decTh[(size_t)q0 * NB + r * 8];
        float dcur = d0;
        #pragma unroll
        for (int t = 0; t < 4; t++) {
            uint4 hvn; float dnx = 0.f;
            if (t < 3) {
                int kk = (t + 1) * 8 + g;
                dnx = __shfl_sync(0xffffffffu, d_r, kk);
                int q = __shfl_sync(0xffffffffu, q_r, kk);
                hvn = *(const uint4*)&g_decTh[(size_t)q * NB + r * 8];
            }
            __half2 md2h = __float2half2_rn(-dcur * dcur);
            const __half2* dh = (const __half2*)&hv;
            __half2 acc2 = zero2;
            #pragma unroll
            for (int j = 0; j < 4; j++) {
                __half2 w = __hmax2(__hfma2(md2h, ah[j], one2), zero2);
                acc2 = __hfma2(__hmul2(w, Eh[t * 4 + j]), dh[j], acc2);
            }
            float2 fa = __half22float2(acc2);       // flush each round (8 terms)
            acc += fa.x + fa.y;
            hv = hvn; dcur = dnx;
        }
        #pragma unroll
        for (int o = 16; o; o >>= 1) acc += __shfl_xor_sync(0xffffffffu, acc, o);
        if (lane == 0) out[p] = acc * (1.0f / 256.0f);

        if (pn >= NN) break;
        p = pn; d_r = dn; q_r = qn; c = cn;
    }
}

extern "C" void kernel_launch(void* const* d_in, const int* in_sizes, int n_in,
                              void* d_out, int out_size) {
    const float* x    = (const float*)d_in[0];
    const float* encW = (const float*)d_in[1];
    const float* encB = (const float*)d_in[2];
    const float* dec  = (const float*)d_in[3];
    const float* bwW  = (const float*)d_in[4];
    const float* bwB  = (const float*)d_in[5];
    const float* nd   = (const float*)d_in[6];
    const int*   nidp = (const int*)d_in[7];
    const int*   lab  = (const int*)d_in[8];
    float* out = (float*)d_out;

    k_prep<<<NN / 32 + 128, 256>>>(dec, x, encW);
    k_bw<<<16, 1024>>>(bwW, bwB, encB);
    k_sumS<<<888, 256>>>(nd, lab);
    k_out<<<740, 256>>>(nd, nidp, lab, out);
}

// round 8
// speedup vs baseline: 1.2586x; 1.2309x over previous
#include <cuda_runtime.h>
#include <cuda_fp16.h>

#define NN 100000
#define NB 32      // n (bases)
#define MM 16      // m (clusters)
#define KK 32      // k (neighbours)

// ---- device scratch (no allocations allowed) ----
__device__ float g_encPart[4 * NB];
__device__ float g_encoded[NB];
__device__ float g_S[NB * KK];
__device__ __align__(16) float g_a[MM * NB];
__device__ __align__(128) __half g_decTh[(size_t)NN * NB];  // decoder^T fp16 [N][32]

// ---- k1: fused transpose (blocks 0..3124) + encode partials ----
__global__ void k_prep(const float* __restrict__ dec, const float* __restrict__ x,
                       const float* __restrict__ W) {
    if (blockIdx.x < NN / 32) {
        __shared__ float tile[32][33];
        int p0 = blockIdx.x * 32;
        int tx = threadIdx.x & 31, ty = threadIdx.x >> 5;
        #pragma unroll
        for (int r = 0; r < 4; r++) {
            int i = ty + 8 * r;
            tile[i][tx] = dec[(size_t)i * NN + p0 + tx];
        }
        __syncthreads();
        #pragma unroll
        for (int r = 0; r < 4; r++) {
            int row = ty + 8 * r;
            g_decTh[(size_t)(p0 + row) * NB + tx] = __float2half(tile[tx][row]);
        }
    } else {
        int e = blockIdx.x - NN / 32;
        int ck = e >> 5, i = e & 31;
        const float* Wr = W + (size_t)i * NN;
        int p0 = ck * (NN / 4);
        float acc = 0.f;
        for (int p = p0 + threadIdx.x; p < p0 + NN / 4; p += 256)
            acc = fmaf(x[p], Wr[p], acc);
        #pragma unroll
        for (int o = 16; o; o >>= 1) acc += __shfl_xor_sync(0xffffffffu, acc, o);
        __shared__ float s[8];
        if ((threadIdx.x & 31) == 0) s[threadIdx.x >> 5] = acc;
        __syncthreads();
        if (threadIdx.x == 0) {
            float t = 0.f;
            #pragma unroll
            for (int j = 0; j < 8; j++) t += s[j];
            g_encPart[ck * NB + i] = t;
        }
    }
}

// ---- k2: finalize encoded, zero S, warp-per-j bw linear -> g_a ----
__global__ void k_bw(const float* __restrict__ bwW, const float* __restrict__ bwB,
                     const float* __restrict__ encB) {
    __shared__ float enc[NB];
    int tid = threadIdx.x;
    if (tid < NB) {
        float e = encB[tid];
        #pragma unroll
        for (int c2 = 0; c2 < 4; c2++) e += g_encPart[c2 * NB + tid];
        enc[tid] = e;
        if (blockIdx.x == 0) g_encoded[tid] = e;
    }
    if (blockIdx.x == 0 && tid < NB * KK) g_S[tid] = 0.f;
    __syncthreads();
    int w = tid >> 5, lane = tid & 31;
    int j = blockIdx.x * 32 + w;
    float z = bwW[j * NB + lane] * enc[lane];
    #pragma unroll
    for (int o = 16; o; o >>= 1) z += __shfl_xor_sync(0xffffffffu, z, o);
    if (lane == 0) {
        z += bwB[j];
        float s = 1.f / (1.f + expf(-z));
        float t = s * (100.0f / 60.0f);
        int i = j >> 4, c = j & 15;
        g_a[c * NB + i] = 1.f / (t * t);
    }
}

// ---- k3: S[i][kk] = sum_p relu(1 - d^2 * a[i, label[p]])  (R4 scalar form) ----
__global__ void __launch_bounds__(256, 6)
k_sumS(const float* __restrict__ nd, const int* __restrict__ lab) {
    __shared__ __align__(16) float sa[MM * NB];
    __shared__ float bS[NB * KK];
    for (int t = threadIdx.x; t < MM * NB; t += 256) sa[t] = g_a[t];
    for (int t = threadIdx.x; t < NB * KK; t += 256) bS[t] = 0.f;
    __syncthreads();

    int lane = threadIdx.x & 31;                    // lane == kk
    int gw = (blockIdx.x * 256 + threadIdx.x) >> 5;
    int h = gw & 1;                                 // which i-half
    int stream = gw >> 1;
    const int nstream = (gridDim.x * 8) >> 1;

    float acc[16];
    #pragma unroll
    for (int ii = 0; ii < 16; ii++) acc[ii] = 0.f;

    int p = stream;
    if (p < NN) {
        float d = nd[p * KK + lane];
        int c = lab[p];
        while (true) {
            int pn = p + nstream;
            float dn = 0.f; int cn = 0;
            if (pn < NN) { dn = nd[pn * KK + lane]; cn = lab[pn]; }
            float md2 = -d * d;
            const float4* a4 = (const float4*)&sa[c * NB + h * 16];
            #pragma unroll
            for (int q = 0; q < 4; q++) {
                float4 av = a4[q];
                acc[q * 4 + 0] += fmaxf(fmaf(md2, av.x, 1.f), 0.f);
                acc[q * 4 + 1] += fmaxf(fmaf(md2, av.y, 1.f), 0.f);
                acc[q * 4 + 2] += fmaxf(fmaf(md2, av.z, 1.f), 0.f);
                acc[q * 4 + 3] += fmaxf(fmaf(md2, av.w, 1.f), 0.f);
            }
            if (pn >= NN) break;
            p = pn; d = dn; c = cn;
        }
    }
    #pragma unroll
    for (int ii = 0; ii < 16; ii++)
        atomicAdd(&bS[(h * 16 + ii) * KK + lane], acc[ii]);
    __syncthreads();
    for (int t = threadIdx.x; t < NB * KK; t += 256)
        atomicAdd(&g_S[t], bS[t]);
}

// ---- k4: out[p] = sum_kk sum_i E*relu(1-d^2 a)*decTh[nid], inner math half2 ----
// E scaled by 256 (exact power of 2, removed at the end); a clamped+packed half2.
__global__ void __launch_bounds__(256, 5)
k_out(const float* __restrict__ nd, const int* __restrict__ nid,
      const int* __restrict__ lab, float* __restrict__ out) {
    __shared__ __half2 sah[MM * 16];
    __shared__ __align__(16) float sE[KK * NB];     // 256*E [kk][i] staging
    for (int t = threadIdx.x; t < MM * 16; t += blockDim.x) {
        int c = t >> 4, j = t & 15;
        float a0 = fminf(g_a[c * NB + j * 2 + 0], 60000.f);
        float a1 = fminf(g_a[c * NB + j * 2 + 1], 60000.f);
        sah[t] = __floats2half2_rn(a0, a1);
    }
    for (int t = threadIdx.x; t < KK * NB; t += blockDim.x) {
        int i = t & 31, kk = t >> 5;
        sE[t] = 256.0f * g_encoded[i] / g_S[i * KK + kk];
    }
    __syncthreads();

    int lane = threadIdx.x & 31;
    int warp = (blockIdx.x * blockDim.x + threadIdx.x) >> 5;
    int nwarp = (gridDim.x * blockDim.x) >> 5;
    int r = lane & 3;        // i-chunk (8 halves = 16B of the 64B row)
    int g = lane >> 2;       // kk subgroup (8 per round)
    const float4* sE4 = (const float4*)sE;
    const __half2 one2 = __float2half2_rn(1.f);
    const __half2 zero2 = __float2half2_rn(0.f);

    // hoist scaled E into 16 half2 registers (born packed, used packed)
    __half2 Eh[16];
    #pragma unroll
    for (int t = 0; t < 4; t++) {
        int kk = t * 8 + g;
        float4 e0 = sE4[kk * 8 + r * 2];
        float4 e1 = sE4[kk * 8 + r * 2 + 1];
        Eh[t * 4 + 0] = __floats2half2_rn(e0.x, e0.y);
        Eh[t * 4 + 1] = __floats2half2_rn(e0.z, e0.w);
        Eh[t * 4 + 2] = __floats2half2_rn(e1.x, e1.y);
        Eh[t * 4 + 3] = __floats2half2_rn(e1.z, e1.w);
    }

    int p = warp;
    if (p >= NN) return;
    float d_r = nd[p * KK + lane];
    int   q_r = nid[p * KK + lane];
    int   c   = lab[p];

    while (true) {
        int pn = p + nwarp;
        float dn = 0.f; int qn = 0, cn = 0;
        if (pn < NN) {
            dn = nd[pn * KK + lane];
            qn = nid[pn * KK + lane];
            cn = lab[pn];
        }

        // this lane's 4 half2 of a (8 i-values) for this point's cluster
        uint4 araw = *(const uint4*)&sah[c * 16 + r * 4];
        const __half2* ah = (const __half2*)&araw;
        float acc = 0.f;

        // 2-stage gather pipeline over the 4 rounds
        float d0 = __shfl_sync(0xffffffffu, d_r, g);
        int   q0 = __shfl_sync(0xffffffffu, q_r, g);
        uint4 hv = *(const uint4*)&g_decTh[(size_t)q0 * NB + r * 8];
        float dcur = d0;
        #pragma unroll
        for (int t = 0; t < 4; t++) {
            uint4 hvn; float dnx = 0.f;
            if (t < 3) {
                int kk = (t + 1) * 8 + g;
                dnx = __shfl_sync(0xffffffffu, d_r, kk);
                int q = __shfl_sync(0xffffffffu, q_r, kk);
                hvn = *(const uint4*)&g_decTh[(size_t)q * NB + r * 8];
            }
            __half2 md2h = __float2half2_rn(-dcur * dcur);
            const __half2* dh = (const __half2*)&hv;
            __half2 acc2 = zero2;
            #pragma unroll
            for (int j = 0; j < 4; j++) {
                __half2 w = __hmax2(__hfma2(md2h, ah[j], one2), zero2);
                acc2 = __hfma2(__hmul2(w, Eh[t * 4 + j]), dh[j], acc2);
            }
            float2 fa = __half22float2(acc2);       // flush each round (8 terms)
            acc += fa.x + fa.y;
            hv = hvn; dcur = dnx;
        }
        #pragma unroll
        for (int o = 16; o; o >>= 1) acc += __shfl_xor_sync(0xffffffffu, acc, o);
        if (lane == 0) out[p] = acc * (1.0f / 256.0f);

        if (pn >= NN) break;
        p = pn; d_r = dn; q_r = qn; c = cn;
    }
}

extern "C" void kernel_launch(void* const* d_in, const int* in_sizes, int n_in,
                              void* d_out, int out_size) {
    const float* x    = (const float*)d_in[0];
    const float* encW = (const float*)d_in[1];
    const float* encB = (const float*)d_in[2];
    const float* dec  = (const float*)d_in[3];
    const float* bwW  = (const float*)d_in[4];
    const float* bwB  = (const float*)d_in[5];
    const float* nd   = (const float*)d_in[6];
    const int*   nidp = (const int*)d_in[7];
    const int*   lab  = (const int*)d_in[8];
    float* out = (float*)d_out;

    k_prep<<<NN / 32 + 128, 256>>>(dec, x, encW);
    k_bw<<<16, 1024>>>(bwW, bwB, encB);
    k_sumS<<<888, 256>>>(nd, lab);
    k_out<<<740, 256>>>(nd, nidp, lab, out);
}